// round 4
// baseline (speedup 1.0000x reference)
#include <cuda_runtime.h>

#define N_NODES 100000
#define MAX_E   800000
#define HID     256

// ---- scratch (static __device__ globals; no allocation) ----
__device__ __align__(16) float g_bufA[(size_t)N_NODES * HID];   // 102.4 MB
__device__ __align__(16) float g_bufB[(size_t)N_NODES * HID];   // 102.4 MB
__device__ float g_dinv[N_NODES];
__device__ int   g_cnt[N_NODES];
__device__ int   g_cur[N_NODES];
__device__ int   g_rowptr[N_NODES + 1];
__device__ int   g_col[MAX_E];

// compile-time buffer selection (no host-side symbol lookup needed)
template<int SEL>
__device__ __forceinline__ const float* sel_in(const float* ext) {
    if (SEL == 0) return g_bufA;
    if (SEL == 1) return g_bufB;
    return ext;
}
template<int SEL>
__device__ __forceinline__ float* sel_out(float* ext) {
    if (SEL == 0) return g_bufA;
    if (SEL == 1) return g_bufB;
    return ext;
}

// ---------------------------------------------------------------- init
__global__ void init_kernel() {
    int i = blockIdx.x * blockDim.x + threadIdx.x;
    if (i < N_NODES) { g_cnt[i] = 0; g_cur[i] = 0; }
}

// ---------------------------------------------------------------- degree count (edge_index is int32)
__global__ void count_kernel(const int* __restrict__ dst, int E) {
    int e = blockIdx.x * blockDim.x + threadIdx.x;
    if (e < E) {
        int d = dst[e];
        if (d >= 0 && d < N_NODES) atomicAdd(&g_cnt[d], 1);
    }
}

// ---------------------------------------------------------------- dinv = rsqrt(deg+1)
__global__ void dinv_kernel() {
    int i = blockIdx.x * blockDim.x + threadIdx.x;
    if (i < N_NODES) g_dinv[i] = rsqrtf((float)g_cnt[i] + 1.0f);
}

// ---------------------------------------------------------------- exclusive scan -> rowptr
__global__ void scan_kernel() {
    __shared__ int wsum[32];
    __shared__ int carry_s;
    int t = threadIdx.x, lane = t & 31, wid = t >> 5;
    if (t == 0) { carry_s = 0; g_rowptr[0] = 0; }
    __syncthreads();
    for (int base = 0; base < N_NODES; base += 1024) {
        int i = base + t;
        int val = (i < N_NODES) ? g_cnt[i] : 0;
        #pragma unroll
        for (int off = 1; off < 32; off <<= 1) {
            int n = __shfl_up_sync(0xffffffffu, val, off);
            if (lane >= off) val += n;
        }
        if (lane == 31) wsum[wid] = val;
        __syncthreads();
        if (wid == 0) {
            int wv = wsum[lane];
            #pragma unroll
            for (int off = 1; off < 32; off <<= 1) {
                int n = __shfl_up_sync(0xffffffffu, wv, off);
                if (lane >= off) wv += n;
            }
            wsum[lane] = wv;
        }
        __syncthreads();
        int pre  = (wid > 0) ? wsum[wid - 1] : 0;
        int incl = val + pre;
        int c    = carry_s;
        if (i < N_NODES) g_rowptr[i + 1] = c + incl;
        __syncthreads();
        if (t == 1023) carry_s = c + incl;
        __syncthreads();
    }
}

// ---------------------------------------------------------------- scatter edges into CSR
__global__ void scatter_kernel(const int* __restrict__ src,
                               const int* __restrict__ dst, int E) {
    int e = blockIdx.x * blockDim.x + threadIdx.x;
    if (e < E) {
        int d = dst[e];
        int s = src[e];
        if (d >= 0 && d < N_NODES && s >= 0 && s < N_NODES) {
            int p = atomicAdd(&g_cur[d], 1);
            g_col[g_rowptr[d] + p] = s;
        }
    }
}

// ---------------------------------------------------------------- aggregation: out = A_norm @ act(in)
// warp-per-node; COLS = 128 or 256; each lane owns COLS/32 consecutive floats
template<int COLS, bool RELU, int INSEL, int OUTSEL>
__global__ void agg_kernel(const float* __restrict__ in_ext, float* __restrict__ out_ext) {
    const float* in  = sel_in<INSEL>(in_ext);
    float*       out = sel_out<OUTSEL>(out_ext);
    int gw   = (blockIdx.x * blockDim.x + threadIdx.x) >> 5;
    int lane = threadIdx.x & 31;
    if (gw >= N_NODES) return;
    constexpr int V  = COLS / 32;   // floats per lane (4 or 8)
    constexpr int NV = V / 4;       // float4 per lane (1 or 2)
    float4 acc[NV];
    #pragma unroll
    for (int q = 0; q < NV; q++) acc[q] = make_float4(0.f, 0.f, 0.f, 0.f);
    const int base = lane * V;
    int rs = __ldg(&g_rowptr[gw]);
    int re = __ldg(&g_rowptr[gw + 1]);
    for (int e = rs; e < re; e++) {
        int   s = g_col[e];
        float w = g_dinv[s];
        const float4* p = reinterpret_cast<const float4*>(in + (size_t)s * COLS + base);
        #pragma unroll
        for (int q = 0; q < NV; q++) {
            float4 v = p[q];
            if (RELU) {
                v.x = fmaxf(v.x, 0.f); v.y = fmaxf(v.y, 0.f);
                v.z = fmaxf(v.z, 0.f); v.w = fmaxf(v.w, 0.f);
            }
            acc[q].x += w * v.x; acc[q].y += w * v.y;
            acc[q].z += w * v.z; acc[q].w += w * v.w;
        }
    }
    float di = g_dinv[gw];
    const float4* ps = reinterpret_cast<const float4*>(in + (size_t)gw * COLS + base);
    #pragma unroll
    for (int q = 0; q < NV; q++) {
        float4 v = ps[q];
        if (RELU) {
            v.x = fmaxf(v.x, 0.f); v.y = fmaxf(v.y, 0.f);
            v.z = fmaxf(v.z, 0.f); v.w = fmaxf(v.w, 0.f);
        }
        acc[q].x += di * v.x; acc[q].y += di * v.y;
        acc[q].z += di * v.z; acc[q].w += di * v.w;
    }
    float4* po = reinterpret_cast<float4*>(out + (size_t)gw * COLS + base);
    #pragma unroll
    for (int q = 0; q < NV; q++) {
        acc[q].x *= di; acc[q].y *= di; acc[q].z *= di; acc[q].w *= di;
        po[q] = acc[q];
    }
}

// ---------------------------------------------------------------- SGEMM + bias (packed f32x2 FMA)
// C[M,256] = A[M,K] @ W[K,256] + bias ; tile 128x128, BK=16, 256 thr, 8x8 microtile
template<int K, int INSEL, int OUTSEL>
__global__ __launch_bounds__(256, 2)
void gemm_bias_kernel(const float* __restrict__ A_ext, const float* __restrict__ B,
                      const float* __restrict__ bias, float* __restrict__ C_ext) {
    const float* A = sel_in<INSEL>(A_ext);
    float*       C = sel_out<OUTSEL>(C_ext);
    __shared__ __align__(16) float As[16][132];
    __shared__ __align__(16) float Bs[16][132];
    const int M  = N_NODES;
    const int bm = blockIdx.x * 128;
    const int bn = blockIdx.y * 128;
    const int t  = threadIdx.x;
    const int tx = t & 15, ty = t >> 4;

    const int la_r = t >> 2;          // 0..63
    const int la_k = (t & 3) * 4;     // 0,4,8,12
    const int lb_k = t >> 5;          // 0..7
    const int lb_c = (t & 31) * 4;    // 0..124

    int ar0 = bm + la_r;       if (ar0 >= M) ar0 = M - 1;
    int ar1 = bm + la_r + 64;  if (ar1 >= M) ar1 = M - 1;

    unsigned long long acc[2][4][2][2];
    #pragma unroll
    for (int im = 0; im < 2; im++)
        #pragma unroll
        for (int i = 0; i < 4; i++)
            #pragma unroll
            for (int jn = 0; jn < 2; jn++) {
                acc[im][i][jn][0] = 0ull; acc[im][i][jn][1] = 0ull;
            }

    for (int k0 = 0; k0 < K; k0 += 16) {
        float4 a0  = *(const float4*)&A[(size_t)ar0 * K + k0 + la_k];
        float4 a1  = *(const float4*)&A[(size_t)ar1 * K + k0 + la_k];
        float4 bv0 = *(const float4*)&B[(size_t)(k0 + lb_k)     * HID + bn + lb_c];
        float4 bv1 = *(const float4*)&B[(size_t)(k0 + lb_k + 8) * HID + bn + lb_c];
        __syncthreads();
        As[la_k + 0][la_r] = a0.x; As[la_k + 1][la_r] = a0.y;
        As[la_k + 2][la_r] = a0.z; As[la_k + 3][la_r] = a0.w;
        As[la_k + 0][la_r + 64] = a1.x; As[la_k + 1][la_r + 64] = a1.y;
        As[la_k + 2][la_r + 64] = a1.z; As[la_k + 3][la_r + 64] = a1.w;
        *(float4*)&Bs[lb_k][lb_c]     = bv0;
        *(float4*)&Bs[lb_k + 8][lb_c] = bv1;
        __syncthreads();
        #pragma unroll
        for (int k = 0; k < 16; k++) {
            float4 fa0 = *(const float4*)&As[k][ty * 4];
            float4 fa1 = *(const float4*)&As[k][64 + ty * 4];
            ulonglong2 ub0 = *(const ulonglong2*)&Bs[k][tx * 4];
            ulonglong2 ub1 = *(const ulonglong2*)&Bs[k][64 + tx * 4];
            float av[2][4] = {{fa0.x, fa0.y, fa0.z, fa0.w},
                              {fa1.x, fa1.y, fa1.z, fa1.w}};
            #pragma unroll
            for (int im = 0; im < 2; im++)
                #pragma unroll
                for (int i = 0; i < 4; i++) {
                    unsigned long long pa;
                    asm("mov.b64 %0, {%1, %1};" : "=l"(pa) : "f"(av[im][i]));
                    asm("fma.rn.f32x2 %0, %1, %2, %0;" : "+l"(acc[im][i][0][0]) : "l"(pa), "l"(ub0.x));
                    asm("fma.rn.f32x2 %0, %1, %2, %0;" : "+l"(acc[im][i][0][1]) : "l"(pa), "l"(ub0.y));
                    asm("fma.rn.f32x2 %0, %1, %2, %0;" : "+l"(acc[im][i][1][0]) : "l"(pa), "l"(ub1.x));
                    asm("fma.rn.f32x2 %0, %1, %2, %0;" : "+l"(acc[im][i][1][1]) : "l"(pa), "l"(ub1.y));
                }
        }
    }

    float4 bias0 = *(const float4*)&bias[bn + tx * 4];
    float4 bias1 = *(const float4*)&bias[bn + 64 + tx * 4];
    #pragma unroll
    for (int im = 0; im < 2; im++)
        #pragma unroll
        for (int i = 0; i < 4; i++) {
            int r = bm + im * 64 + ty * 4 + i;
            if (r < M) {
                float x0, y0, z0, w0, x1, y1, z1, w1;
                asm("mov.b64 {%0, %1}, %2;" : "=f"(x0), "=f"(y0) : "l"(acc[im][i][0][0]));
                asm("mov.b64 {%0, %1}, %2;" : "=f"(z0), "=f"(w0) : "l"(acc[im][i][0][1]));
                asm("mov.b64 {%0, %1}, %2;" : "=f"(x1), "=f"(y1) : "l"(acc[im][i][1][0]));
                asm("mov.b64 {%0, %1}, %2;" : "=f"(z1), "=f"(w1) : "l"(acc[im][i][1][1]));
                float4 o0 = make_float4(x0 + bias0.x, y0 + bias0.y, z0 + bias0.z, w0 + bias0.w);
                float4 o1 = make_float4(x1 + bias1.x, y1 + bias1.y, z1 + bias1.z, w1 + bias1.w);
                *(float4*)&C[(size_t)r * HID + bn + tx * 4]      = o0;
                *(float4*)&C[(size_t)r * HID + bn + 64 + tx * 4] = o1;
            }
        }
}

// ---------------------------------------------------------------- launch
extern "C" void kernel_launch(void* const* d_in, const int* in_sizes, int n_in,
                              void* d_out, int out_size) {
    const float* x   = (const float*)d_in[0];
    const int*   ei  = (const int*)d_in[1];     // edge_index: int32 (JAX x64 disabled)
    const float* W1  = (const float*)d_in[2];
    const float* b1  = (const float*)d_in[3];
    const float* W2  = (const float*)d_in[4];
    const float* b2  = (const float*)d_in[5];
    const float* W3  = (const float*)d_in[6];
    const float* b3  = (const float*)d_in[7];
    float*       out = (float*)d_out;

    const int E = in_sizes[1] / 2;
    const int* src = ei;
    const int* dst = ei + E;

    const int TB = 256;
    const int nb_nodes = (N_NODES + TB - 1) / TB;
    const int nb_edges = (E + TB - 1) / TB;
    const int nb_agg   = (N_NODES * 32 + TB - 1) / TB;   // warp per node
    dim3 gemm_grid((N_NODES + 127) / 128, 2);

    // preprocessing (CSR + dinv), recomputed every call (deterministic)
    init_kernel<<<nb_nodes, TB>>>();
    count_kernel<<<nb_edges, TB>>>(dst, E);
    dinv_kernel<<<nb_nodes, TB>>>();
    scan_kernel<<<1, 1024>>>();
    scatter_kernel<<<nb_edges, TB>>>(src, dst, E);

    // layer 1: agg(x)[N,128] -> bufA; gemm K=128 bufA -> bufB
    agg_kernel<128, false, -1, 0><<<nb_agg, TB>>>(x, nullptr);
    gemm_bias_kernel<128, 0, 1><<<gemm_grid, TB>>>(nullptr, W1, b1, nullptr);

    // layer 2: agg(relu(bufB)) -> bufA; gemm K=256 bufA -> bufB
    agg_kernel<256, true, 1, 0><<<nb_agg, TB>>>(nullptr, nullptr);
    gemm_bias_kernel<256, 0, 1><<<gemm_grid, TB>>>(nullptr, W2, b2, nullptr);

    // layer 3: agg(relu(bufB)) -> bufA; gemm K=256 bufA -> out
    agg_kernel<256, true, 1, 0><<<nb_agg, TB>>>(nullptr, nullptr);
    gemm_bias_kernel<256, 0, -1><<<gemm_grid, TB>>>(nullptr, W3, b3, out);
}

// round 6
// speedup vs baseline: 1.4083x; 1.4083x over previous
#include <cuda_runtime.h>
#include <cuda_bf16.h>
#include <cstdint>

#define N_NODES 100000
#define MAX_E   800000
#define HID     256
#define NB_SCAN 98          // ceil(100000/1024)

// ---- scratch (static __device__ globals; no allocation) ----
__device__ __align__(16) float          g_h[(size_t)N_NODES * HID];      // fp32 layer output
__device__ __align__(16) __nv_bfloat16  g_ahi[(size_t)N_NODES * HID];    // gemm A hi
__device__ __align__(16) __nv_bfloat16  g_alo[(size_t)N_NODES * HID];    // gemm A lo
__device__ __align__(16) __nv_bfloat16  g_wthi[HID * HID];               // W^T hi [N=256, K]
__device__ __align__(16) __nv_bfloat16  g_wtlo[HID * HID];               // W^T lo
__device__ float g_dinv[N_NODES];
__device__ int   g_cnt[N_NODES];
__device__ int   g_cur[N_NODES];
__device__ int   g_rowptr[N_NODES + 1];
__device__ int   g_col[MAX_E];
__device__ int   g_part[128];

template<int SEL>
__device__ __forceinline__ const float* sel_in(const float* ext) {
    if (SEL == 1) return g_h;
    return ext;
}
template<int SEL>
__device__ __forceinline__ float* sel_out(float* ext) {
    if (SEL == 1) return g_h;
    return ext;
}

// ================= warp MMA helpers (base-target PTX only) =================
__device__ __forceinline__ uint32_t smem_u32(const void* p) {
    uint32_t a;
    asm("{ .reg .u64 t; cvta.to.shared.u64 t, %1; cvt.u32.u64 %0, t; }" : "=r"(a) : "l"(p));
    return a;
}
__device__ __forceinline__ void ldsm_x4(uint32_t* r, uint32_t addr) {
    asm volatile("ldmatrix.sync.aligned.m8n8.x4.shared.b16 {%0,%1,%2,%3}, [%4];"
        : "=r"(r[0]), "=r"(r[1]), "=r"(r[2]), "=r"(r[3]) : "r"(addr));
}
__device__ __forceinline__ void ldsm_x2(uint32_t* r, uint32_t addr) {
    asm volatile("ldmatrix.sync.aligned.m8n8.x2.shared.b16 {%0,%1}, [%2];"
        : "=r"(r[0]), "=r"(r[1]) : "r"(addr));
}
__device__ __forceinline__ void mma_bf16(float* c, const uint32_t* a, const uint32_t* b) {
    asm volatile("mma.sync.aligned.m16n8k16.row.col.f32.bf16.bf16.f32 "
        "{%0,%1,%2,%3}, {%4,%5,%6,%7}, {%8,%9}, {%0,%1,%2,%3};"
        : "+f"(c[0]), "+f"(c[1]), "+f"(c[2]), "+f"(c[3])
        : "r"(a[0]), "r"(a[1]), "r"(a[2]), "r"(a[3]), "r"(b[0]), "r"(b[1]));
}

// ================= preprocessing =================
__global__ void init_kernel() {
    int i = blockIdx.x * blockDim.x + threadIdx.x;
    if (i < N_NODES) { g_cnt[i] = 0; g_cur[i] = 0; }
}
__global__ void count_kernel(const int* __restrict__ dst, int E) {
    int e = blockIdx.x * blockDim.x + threadIdx.x;
    if (e < E) {
        int d = dst[e];
        if (d >= 0 && d < N_NODES) atomicAdd(&g_cnt[d], 1);
    }
}
__global__ void dinv_kernel() {
    int i = blockIdx.x * blockDim.x + threadIdx.x;
    if (i < N_NODES) g_dinv[i] = rsqrtf((float)g_cnt[i] + 1.0f);
}
__global__ void scan_reduce_kernel() {
    __shared__ int ws[32];
    int t = threadIdx.x, lane = t & 31, wid = t >> 5;
    int i = blockIdx.x * 1024 + t;
    int v = (i < N_NODES) ? g_cnt[i] : 0;
    #pragma unroll
    for (int o = 16; o > 0; o >>= 1) v += __shfl_down_sync(0xffffffffu, v, o);
    if (lane == 0) ws[wid] = v;
    __syncthreads();
    if (wid == 0) {
        int s = ws[lane];
        #pragma unroll
        for (int o = 16; o > 0; o >>= 1) s += __shfl_down_sync(0xffffffffu, s, o);
        if (lane == 0) g_part[blockIdx.x] = s;
    }
}
__global__ void scan_part_kernel() {
    __shared__ int ws[4];
    int t = threadIdx.x, lane = t & 31, wid = t >> 5;
    int v = (t < NB_SCAN) ? g_part[t] : 0;
    int incl = v;
    #pragma unroll
    for (int o = 1; o < 32; o <<= 1) {
        int n = __shfl_up_sync(0xffffffffu, incl, o);
        if (lane >= o) incl += n;
    }
    if (lane == 31) ws[wid] = incl;
    __syncthreads();
    int off = 0;
    for (int j = 0; j < wid; j++) off += ws[j];
    if (t < NB_SCAN) g_part[t] = off + incl - v;   // exclusive
}
__global__ void scan_apply_kernel() {
    __shared__ int ws[32];
    int t = threadIdx.x, lane = t & 31, wid = t >> 5;
    int i = blockIdx.x * 1024 + t;
    int v = (i < N_NODES) ? g_cnt[i] : 0;
    int incl = v;
    #pragma unroll
    for (int o = 1; o < 32; o <<= 1) {
        int n = __shfl_up_sync(0xffffffffu, incl, o);
        if (lane >= o) incl += n;
    }
    if (lane == 31) ws[wid] = incl;
    __syncthreads();
    if (wid == 0) {
        int wv = ws[lane];
        #pragma unroll
        for (int o = 1; o < 32; o <<= 1) {
            int n = __shfl_up_sync(0xffffffffu, wv, o);
            if (lane >= o) wv += n;
        }
        ws[lane] = wv;
    }
    __syncthreads();
    int pre = (wid > 0) ? ws[wid - 1] : 0;
    if (i < N_NODES) g_rowptr[i + 1] = g_part[blockIdx.x] + pre + incl;
    if (i == 0) g_rowptr[0] = 0;
}
__global__ void scatter_kernel(const int* __restrict__ src,
                               const int* __restrict__ dst, int E) {
    int e = blockIdx.x * blockDim.x + threadIdx.x;
    if (e < E) {
        int d = dst[e];
        int s = src[e];
        if (d >= 0 && d < N_NODES && s >= 0 && s < N_NODES) {
            int p = atomicAdd(&g_cur[d], 1);
            g_col[g_rowptr[d] + p] = s;
        }
    }
}

// ================= W transpose + split-bf16 convert =================
__global__ void wconv_kernel(const float* __restrict__ W, int K) {
    int idx = blockIdx.x * blockDim.x + threadIdx.x;
    if (idx < HID * K) {
        int n = idx / K, k = idx % K;
        float v = W[(size_t)k * HID + n];
        __nv_bfloat16 h = __float2bfloat16(v);
        g_wthi[idx] = h;
        g_wtlo[idx] = __float2bfloat16(v - __bfloat162float(h));
    }
}

// ================= aggregation: (A_hi, A_lo) = split_bf16(A_norm @ act(in)) =================
template<int COLS, bool RELU, int INSEL>
__global__ void agg_kernel(const float* __restrict__ in_ext) {
    const float* in = sel_in<INSEL>(in_ext);
    int gw   = (blockIdx.x * blockDim.x + threadIdx.x) >> 5;
    int lane = threadIdx.x & 31;
    if (gw >= N_NODES) return;
    constexpr int V  = COLS / 32;
    constexpr int NV = V / 4;
    float4 acc[NV];
    #pragma unroll
    for (int q = 0; q < NV; q++) acc[q] = make_float4(0.f, 0.f, 0.f, 0.f);
    const int base = lane * V;
    int rs = __ldg(&g_rowptr[gw]);
    int re = __ldg(&g_rowptr[gw + 1]);
    for (int e = rs; e < re; e++) {
        int   s = g_col[e];
        float w = g_dinv[s];
        const float4* p = reinterpret_cast<const float4*>(in + (size_t)s * COLS + base);
        #pragma unroll
        for (int q = 0; q < NV; q++) {
            float4 v = p[q];
            if (RELU) {
                v.x = fmaxf(v.x, 0.f); v.y = fmaxf(v.y, 0.f);
                v.z = fmaxf(v.z, 0.f); v.w = fmaxf(v.w, 0.f);
            }
            acc[q].x += w * v.x; acc[q].y += w * v.y;
            acc[q].z += w * v.z; acc[q].w += w * v.w;
        }
    }
    float di = g_dinv[gw];
    const float4* ps = reinterpret_cast<const float4*>(in + (size_t)gw * COLS + base);
    #pragma unroll
    for (int q = 0; q < NV; q++) {
        float4 v = ps[q];
        if (RELU) {
            v.x = fmaxf(v.x, 0.f); v.y = fmaxf(v.y, 0.f);
            v.z = fmaxf(v.z, 0.f); v.w = fmaxf(v.w, 0.f);
        }
        acc[q].x += di * v.x; acc[q].y += di * v.y;
        acc[q].z += di * v.z; acc[q].w += di * v.w;
    }
    __nv_bfloat162* ph = reinterpret_cast<__nv_bfloat162*>(g_ahi + (size_t)gw * COLS + base);
    __nv_bfloat162* pl = reinterpret_cast<__nv_bfloat162*>(g_alo + (size_t)gw * COLS + base);
    #pragma unroll
    for (int q = 0; q < NV; q++) {
        float a[4] = {acc[q].x * di, acc[q].y * di, acc[q].z * di, acc[q].w * di};
        __nv_bfloat16 h[4], l[4];
        #pragma unroll
        for (int j = 0; j < 4; j++) {
            h[j] = __float2bfloat16(a[j]);
            l[j] = __float2bfloat16(a[j] - __bfloat162float(h[j]));
        }
        ph[q * 2 + 0] = __nv_bfloat162(h[0], h[1]);
        ph[q * 2 + 1] = __nv_bfloat162(h[2], h[3]);
        pl[q * 2 + 0] = __nv_bfloat162(l[0], l[1]);
        pl[q * 2 + 1] = __nv_bfloat162(l[2], l[3]);
    }
}

// ================= HMMA split-bf16 GEMM: C[M,256] = A @ W + bias =================
// A = g_ahi+g_alo [M, K], B = W^T hi/lo [256, K]; CTA tile 128x128, BK=32,
// 8 warps (4 m x 2 n), warp tile 32x64; mma.sync m16n8k16 row.col f32.bf16
#define BKP 40   // padded K stride in bf16 (32+8): conflict-free ldmatrix

template<int K, int OUTSEL>
__global__ __launch_bounds__(256)
void gemm_mma_kernel(const float* __restrict__ bias, float* __restrict__ C_ext) {
    float* C = sel_out<OUTSEL>(C_ext);
    __shared__ __align__(16) __nv_bfloat16 Ah[128][BKP];
    __shared__ __align__(16) __nv_bfloat16 Al[128][BKP];
    __shared__ __align__(16) __nv_bfloat16 Bh[128][BKP];
    __shared__ __align__(16) __nv_bfloat16 Bl[128][BKP];

    const int M   = N_NODES;
    const int tid = threadIdx.x;
    const int wid = tid >> 5, lane = tid & 31;
    const int bm  = blockIdx.x * 128;
    const int bn  = blockIdx.y * 128;
    const int warp_m = wid & 3;        // 0..3 -> 32 rows each
    const int warp_n = wid >> 2;       // 0..1 -> 64 cols each

    float acc[2][8][4];
    #pragma unroll
    for (int mt = 0; mt < 2; mt++)
        #pragma unroll
        for (int nt = 0; nt < 8; nt++)
            #pragma unroll
            for (int q = 0; q < 4; q++) acc[mt][nt][q] = 0.f;

    // ldmatrix source addresses (per-lane)
    const int a_row = warp_m * 32 + (lane & 15);
    const int a_kof = (lane >> 4) * 8;
    const int b_row = warp_n * 64 + (lane & 7);
    const int b_kof = ((lane >> 3) & 1) * 8;

    for (int c = 0; c < K / 32; c++) {
        const int k0 = c * 32;
        // load A: 128 rows x 32 bf16 (hi+lo); 512 16B-chunks each, 256 threads
        #pragma unroll
        for (int it = 0; it < 2; it++) {
            int ch = it * 256 + tid;
            int r = ch >> 2, s = ch & 3;
            int gr = bm + r; if (gr > M - 1) gr = M - 1;
            *(uint4*)&Ah[r][s * 8] = *(const uint4*)&g_ahi[(size_t)gr * K + k0 + s * 8];
            *(uint4*)&Al[r][s * 8] = *(const uint4*)&g_alo[(size_t)gr * K + k0 + s * 8];
        }
        // load B: rows bn..bn+127 of W^T
        #pragma unroll
        for (int it = 0; it < 2; it++) {
            int ch = it * 256 + tid;
            int r = ch >> 2, s = ch & 3;
            *(uint4*)&Bh[r][s * 8] = *(const uint4*)&g_wthi[(size_t)(bn + r) * K + k0 + s * 8];
            *(uint4*)&Bl[r][s * 8] = *(const uint4*)&g_wtlo[(size_t)(bn + r) * K + k0 + s * 8];
        }
        __syncthreads();

        #pragma unroll
        for (int ks = 0; ks < 32; ks += 16) {
            uint32_t ah[2][4], al[2][4];
            #pragma unroll
            for (int mt = 0; mt < 2; mt++) {
                uint32_t ra = smem_u32(&Ah[a_row + mt * 16][ks + a_kof]);
                uint32_t rl = smem_u32(&Al[a_row + mt * 16][ks + a_kof]);
                ldsm_x4(ah[mt], ra);
                ldsm_x4(al[mt], rl);
            }
            #pragma unroll
            for (int nt = 0; nt < 8; nt++) {
                uint32_t bh[2], bl[2];
                ldsm_x2(bh, smem_u32(&Bh[b_row + nt * 8][ks + b_kof]));
                ldsm_x2(bl, smem_u32(&Bl[b_row + nt * 8][ks + b_kof]));
                #pragma unroll
                for (int mt = 0; mt < 2; mt++) {
                    mma_bf16(acc[mt][nt], ah[mt], bh);
                    mma_bf16(acc[mt][nt], ah[mt], bl);
                    mma_bf16(acc[mt][nt], al[mt], bh);
                }
            }
        }
        __syncthreads();
    }

    // epilogue: c0,c1 -> (row t/4, col (t%4)*2 +0/1); c2,c3 -> row+8
    const int er = lane >> 2;
    const int ec = (lane & 3) * 2;
    #pragma unroll
    for (int nt = 0; nt < 8; nt++) {
        int col = bn + warp_n * 64 + nt * 8 + ec;
        float bx = bias[col], by = bias[col + 1];
        #pragma unroll
        for (int mt = 0; mt < 2; mt++) {
            int r0 = bm + warp_m * 32 + mt * 16 + er;
            if (r0 < M) {
                float2 o0 = make_float2(acc[mt][nt][0] + bx, acc[mt][nt][1] + by);
                *(float2*)&C[(size_t)r0 * HID + col] = o0;
            }
            int r1 = r0 + 8;
            if (r1 < M) {
                float2 o1 = make_float2(acc[mt][nt][2] + bx, acc[mt][nt][3] + by);
                *(float2*)&C[(size_t)r1 * HID + col] = o1;
            }
        }
    }
}

// ================= launch =================
extern "C" void kernel_launch(void* const* d_in, const int* in_sizes, int n_in,
                              void* d_out, int out_size) {
    const float* x   = (const float*)d_in[0];
    const int*   ei  = (const int*)d_in[1];
    const float* W1  = (const float*)d_in[2];
    const float* b1  = (const float*)d_in[3];
    const float* W2  = (const float*)d_in[4];
    const float* b2  = (const float*)d_in[5];
    const float* W3  = (const float*)d_in[6];
    const float* b3  = (const float*)d_in[7];
    float*       out = (float*)d_out;

    const int E = in_sizes[1] / 2;
    const int* src = ei;
    const int* dst = ei + E;

    const int TB = 256;
    const int nb_nodes = (N_NODES + TB - 1) / TB;
    const int nb_edges = (E + TB - 1) / TB;
    const int nb_agg   = (N_NODES * 32 + TB - 1) / TB;
    dim3 gemm_grid((N_NODES + 127) / 128, 2);

    // preprocessing: CSR + dinv (parallel scan)
    init_kernel<<<nb_nodes, TB>>>();
    count_kernel<<<nb_edges, TB>>>(dst, E);
    dinv_kernel<<<nb_nodes, TB>>>();
    scan_reduce_kernel<<<NB_SCAN, 1024>>>();
    scan_part_kernel<<<1, 128>>>();
    scan_apply_kernel<<<NB_SCAN, 1024>>>();
    scatter_kernel<<<nb_edges, TB>>>(src, dst, E);

    // layer 1
    wconv_kernel<<<(HID * 128 + 255) / 256, 256>>>(W1, 128);
    agg_kernel<128, false, -1><<<nb_agg, TB>>>(x);
    gemm_mma_kernel<128, 1><<<gemm_grid, 256>>>(b1, nullptr);
    // layer 2
    wconv_kernel<<<(HID * 256 + 255) / 256, 256>>>(W2, 256);
    agg_kernel<256, true, 1><<<nb_agg, TB>>>(nullptr);
    gemm_mma_kernel<256, 1><<<gemm_grid, 256>>>(b2, nullptr);
    // layer 3
    wconv_kernel<<<(HID * 256 + 255) / 256, 256>>>(W3, 256);
    agg_kernel<256, true, 1><<<nb_agg, TB>>>(nullptr);
    gemm_mma_kernel<256, -1><<<gemm_grid, 256>>>(b3, out);
}

// round 7
// speedup vs baseline: 1.5902x; 1.1291x over previous
#include <cuda_runtime.h>
#include <cuda_bf16.h>
#include <cstdint>

#define N_NODES 100000
#define MAX_E   800000
#define HID     256
#define NB_SCAN 98          // ceil(100000/1024)

// ---- scratch (static __device__ globals; no allocation) ----
__device__ __align__(16) float          g_h[(size_t)N_NODES * HID];      // fp32 layer output
__device__ __align__(16) __nv_bfloat16  g_ahi[(size_t)N_NODES * HID];    // gemm A hi
__device__ __align__(16) __nv_bfloat16  g_alo[(size_t)N_NODES * HID];    // gemm A lo
__device__ __align__(16) __nv_bfloat16  g_wthi[HID * HID];               // W^T hi [N=256, K]
__device__ __align__(16) __nv_bfloat16  g_wtlo[HID * HID];               // W^T lo
__device__ float g_dinv[N_NODES];
__device__ int   g_cnt[N_NODES];
__device__ int   g_cur[N_NODES];
__device__ int   g_rowptr[N_NODES + 1];
__device__ int   g_col[MAX_E];
__device__ int   g_part[128];

template<int SEL>
__device__ __forceinline__ const float* sel_in(const float* ext) {
    if (SEL == 1) return g_h;
    return ext;
}
template<int SEL>
__device__ __forceinline__ float* sel_out(float* ext) {
    if (SEL == 1) return g_h;
    return ext;
}

// ================= warp MMA + cp.async helpers (base-target PTX only) =================
__device__ __forceinline__ uint32_t smem_u32(const void* p) {
    uint32_t a;
    asm("{ .reg .u64 t; cvta.to.shared.u64 t, %1; cvt.u32.u64 %0, t; }" : "=r"(a) : "l"(p));
    return a;
}
__device__ __forceinline__ void ldsm_x4(uint32_t* r, uint32_t addr) {
    asm volatile("ldmatrix.sync.aligned.m8n8.x4.shared.b16 {%0,%1,%2,%3}, [%4];"
        : "=r"(r[0]), "=r"(r[1]), "=r"(r[2]), "=r"(r[3]) : "r"(addr));
}
__device__ __forceinline__ void ldsm_x2(uint32_t* r, uint32_t addr) {
    asm volatile("ldmatrix.sync.aligned.m8n8.x2.shared.b16 {%0,%1}, [%2];"
        : "=r"(r[0]), "=r"(r[1]) : "r"(addr));
}
__device__ __forceinline__ void mma_bf16(float* c, const uint32_t* a, const uint32_t* b) {
    asm volatile("mma.sync.aligned.m16n8k16.row.col.f32.bf16.bf16.f32 "
        "{%0,%1,%2,%3}, {%4,%5,%6,%7}, {%8,%9}, {%0,%1,%2,%3};"
        : "+f"(c[0]), "+f"(c[1]), "+f"(c[2]), "+f"(c[3])
        : "r"(a[0]), "r"(a[1]), "r"(a[2]), "r"(a[3]), "r"(b[0]), "r"(b[1]));
}
__device__ __forceinline__ void cp16(uint32_t dst, const void* src) {
    asm volatile("cp.async.cg.shared.global [%0], [%1], 16;" :: "r"(dst), "l"(src));
}
#define CP_COMMIT() asm volatile("cp.async.commit_group;" ::: "memory")
#define CP_WAIT0()  asm volatile("cp.async.wait_group 0;" ::: "memory")

// ================= preprocessing =================
__global__ void init_kernel() {
    int i = blockIdx.x * blockDim.x + threadIdx.x;
    if (i < N_NODES) { g_cnt[i] = 0; g_cur[i] = 0; }
}
__global__ void count_kernel(const int* __restrict__ dst, int E) {
    int e = blockIdx.x * blockDim.x + threadIdx.x;
    if (e < E) {
        int d = dst[e];
        if (d >= 0 && d < N_NODES) atomicAdd(&g_cnt[d], 1);
    }
}
__global__ void dinv_kernel() {
    int i = blockIdx.x * blockDim.x + threadIdx.x;
    if (i < N_NODES) g_dinv[i] = rsqrtf((float)g_cnt[i] + 1.0f);
}
__global__ void scan_reduce_kernel() {
    __shared__ int ws[32];
    int t = threadIdx.x, lane = t & 31, wid = t >> 5;
    int i = blockIdx.x * 1024 + t;
    int v = (i < N_NODES) ? g_cnt[i] : 0;
    #pragma unroll
    for (int o = 16; o > 0; o >>= 1) v += __shfl_down_sync(0xffffffffu, v, o);
    if (lane == 0) ws[wid] = v;
    __syncthreads();
    if (wid == 0) {
        int s = ws[lane];
        #pragma unroll
        for (int o = 16; o > 0; o >>= 1) s += __shfl_down_sync(0xffffffffu, s, o);
        if (lane == 0) g_part[blockIdx.x] = s;
    }
}
__global__ void scan_part_kernel() {
    __shared__ int ws[4];
    int t = threadIdx.x, lane = t & 31, wid = t >> 5;
    int v = (t < NB_SCAN) ? g_part[t] : 0;
    int incl = v;
    #pragma unroll
    for (int o = 1; o < 32; o <<= 1) {
        int n = __shfl_up_sync(0xffffffffu, incl, o);
        if (lane >= o) incl += n;
    }
    if (lane == 31) ws[wid] = incl;
    __syncthreads();
    int off = 0;
    for (int j = 0; j < wid; j++) off += ws[j];
    if (t < NB_SCAN) g_part[t] = off + incl - v;   // exclusive
}
__global__ void scan_apply_kernel() {
    __shared__ int ws[32];
    int t = threadIdx.x, lane = t & 31, wid = t >> 5;
    int i = blockIdx.x * 1024 + t;
    int v = (i < N_NODES) ? g_cnt[i] : 0;
    int incl = v;
    #pragma unroll
    for (int o = 1; o < 32; o <<= 1) {
        int n = __shfl_up_sync(0xffffffffu, incl, o);
        if (lane >= o) incl += n;
    }
    if (lane == 31) ws[wid] = incl;
    __syncthreads();
    if (wid == 0) {
        int wv = ws[lane];
        #pragma unroll
        for (int o = 1; o < 32; o <<= 1) {
            int n = __shfl_up_sync(0xffffffffu, wv, o);
            if (lane >= o) wv += n;
        }
        ws[lane] = wv;
    }
    __syncthreads();
    int pre = (wid > 0) ? ws[wid - 1] : 0;
    if (i < N_NODES) g_rowptr[i + 1] = g_part[blockIdx.x] + pre + incl;
    if (i == 0) g_rowptr[0] = 0;
}
__global__ void scatter_kernel(const int* __restrict__ src,
                               const int* __restrict__ dst, int E) {
    int e = blockIdx.x * blockDim.x + threadIdx.x;
    if (e < E) {
        int d = dst[e];
        int s = src[e];
        if (d >= 0 && d < N_NODES && s >= 0 && s < N_NODES) {
            int p = atomicAdd(&g_cur[d], 1);
            g_col[g_rowptr[d] + p] = s;
        }
    }
}

// ================= W transpose + split-bf16 convert =================
__global__ void wconv_kernel(const float* __restrict__ W, int K) {
    int idx = blockIdx.x * blockDim.x + threadIdx.x;
    if (idx < HID * K) {
        int n = idx / K, k = idx % K;
        float v = W[(size_t)k * HID + n];
        __nv_bfloat16 h = __float2bfloat16(v);
        g_wthi[idx] = h;
        g_wtlo[idx] = __float2bfloat16(v - __bfloat162float(h));
    }
}

// ================= aggregation: (A_hi, A_lo) = split_bf16(A_norm @ act(in)) =================
template<int COLS, bool RELU, int INSEL>
__global__ void agg_kernel(const float* __restrict__ in_ext) {
    const float* in = sel_in<INSEL>(in_ext);
    int gw   = (blockIdx.x * blockDim.x + threadIdx.x) >> 5;
    int lane = threadIdx.x & 31;
    if (gw >= N_NODES) return;
    constexpr int V  = COLS / 32;
    constexpr int NV = V / 4;
    float4 acc[NV];
    #pragma unroll
    for (int q = 0; q < NV; q++) acc[q] = make_float4(0.f, 0.f, 0.f, 0.f);
    const int base = lane * V;
    int rs = __ldg(&g_rowptr[gw]);
    int re = __ldg(&g_rowptr[gw + 1]);
    int e = rs;
    // 2-edge unroll: doubles outstanding LDG.128s
    for (; e + 1 < re; e += 2) {
        int   s0 = g_col[e],     s1 = g_col[e + 1];
        float w0 = g_dinv[s0],   w1 = g_dinv[s1];
        const float4* p0 = reinterpret_cast<const float4*>(in + (size_t)s0 * COLS + base);
        const float4* p1 = reinterpret_cast<const float4*>(in + (size_t)s1 * COLS + base);
        #pragma unroll
        for (int q = 0; q < NV; q++) {
            float4 v0 = p0[q], v1 = p1[q];
            if (RELU) {
                v0.x = fmaxf(v0.x, 0.f); v0.y = fmaxf(v0.y, 0.f);
                v0.z = fmaxf(v0.z, 0.f); v0.w = fmaxf(v0.w, 0.f);
                v1.x = fmaxf(v1.x, 0.f); v1.y = fmaxf(v1.y, 0.f);
                v1.z = fmaxf(v1.z, 0.f); v1.w = fmaxf(v1.w, 0.f);
            }
            acc[q].x += w0 * v0.x + w1 * v1.x;
            acc[q].y += w0 * v0.y + w1 * v1.y;
            acc[q].z += w0 * v0.z + w1 * v1.z;
            acc[q].w += w0 * v0.w + w1 * v1.w;
        }
    }
    if (e < re) {
        int   s = g_col[e];
        float w = g_dinv[s];
        const float4* p = reinterpret_cast<const float4*>(in + (size_t)s * COLS + base);
        #pragma unroll
        for (int q = 0; q < NV; q++) {
            float4 v = p[q];
            if (RELU) {
                v.x = fmaxf(v.x, 0.f); v.y = fmaxf(v.y, 0.f);
                v.z = fmaxf(v.z, 0.f); v.w = fmaxf(v.w, 0.f);
            }
            acc[q].x += w * v.x; acc[q].y += w * v.y;
            acc[q].z += w * v.z; acc[q].w += w * v.w;
        }
    }
    float di = g_dinv[gw];
    const float4* ps = reinterpret_cast<const float4*>(in + (size_t)gw * COLS + base);
    #pragma unroll
    for (int q = 0; q < NV; q++) {
        float4 v = ps[q];
        if (RELU) {
            v.x = fmaxf(v.x, 0.f); v.y = fmaxf(v.y, 0.f);
            v.z = fmaxf(v.z, 0.f); v.w = fmaxf(v.w, 0.f);
        }
        acc[q].x += di * v.x; acc[q].y += di * v.y;
        acc[q].z += di * v.z; acc[q].w += di * v.w;
    }
    __nv_bfloat162* ph = reinterpret_cast<__nv_bfloat162*>(g_ahi + (size_t)gw * COLS + base);
    __nv_bfloat162* pl = reinterpret_cast<__nv_bfloat162*>(g_alo + (size_t)gw * COLS + base);
    #pragma unroll
    for (int q = 0; q < NV; q++) {
        float a[4] = {acc[q].x * di, acc[q].y * di, acc[q].z * di, acc[q].w * di};
        __nv_bfloat16 h[4], l[4];
        #pragma unroll
        for (int j = 0; j < 4; j++) {
            h[j] = __float2bfloat16(a[j]);
            l[j] = __float2bfloat16(a[j] - __bfloat162float(h[j]));
        }
        ph[q * 2 + 0] = __nv_bfloat162(h[0], h[1]);
        ph[q * 2 + 1] = __nv_bfloat162(h[2], h[3]);
        pl[q * 2 + 0] = __nv_bfloat162(l[0], l[1]);
        pl[q * 2 + 1] = __nv_bfloat162(l[2], l[3]);
    }
}

// ================= HMMA split-bf16 GEMM, cp.async double-buffered =================
// C[M,256] = A @ W + bias; CTA tile 128x128, BK=32, 8 warps (4m x 2n), warp tile 32x64
#define BKP       40                        // padded K stride (bf16): 80 B (16B-aligned)
#define BUF_BYTES (128 * BKP * 2)           // 10240 B per tile buffer
#define STG_BYTES (4 * BUF_BYTES)           // Ah, Al, Bh, Bl
#define GEMM_SMEM (2 * STG_BYTES)           // 2 stages = 81920 B

template<int K, int OUTSEL>
__global__ __launch_bounds__(256)
void gemm_mma_kernel(const float* __restrict__ bias, float* __restrict__ C_ext) {
    extern __shared__ __align__(16) char dsm[];
    float* C = sel_out<OUTSEL>(C_ext);

    const int M   = N_NODES;
    const int tid = threadIdx.x;
    const int wid = tid >> 5, lane = tid & 31;
    const int bm  = blockIdx.x * 128;
    const int bn  = blockIdx.y * 128;
    const int warp_m = wid & 3;
    const int warp_n = wid >> 2;
    constexpr int NCH = K / 32;

    const uint32_t sb = smem_u32(dsm);
    // per-thread load slots: ch = it*256 + tid -> r = ch>>2, s = ch&3
    const int r0 = tid >> 2, s0 = tid & 3;
    const int r1 = (256 + tid) >> 2, s1 = tid & 3;   // r1 = r0 + 64

    float acc[2][8][4];
    #pragma unroll
    for (int mt = 0; mt < 2; mt++)
        #pragma unroll
        for (int nt = 0; nt < 8; nt++)
            #pragma unroll
            for (int q = 0; q < 4; q++) acc[mt][nt][q] = 0.f;

    const int a_row = warp_m * 32 + (lane & 15);
    const int a_kof = (lane >> 4) * 8;
    const int b_row = warp_n * 64 + (lane & 7);
    const int b_kof = ((lane >> 3) & 1) * 8;

    int gr0 = bm + r0; if (gr0 > M - 1) gr0 = M - 1;
    int gr1 = bm + r1; if (gr1 > M - 1) gr1 = M - 1;

    auto issue = [&](int c, int st) {
        const int k0 = c * 32;
        uint32_t base = sb + st * STG_BYTES;
        uint32_t oA0 = (uint32_t)(r0 * BKP + s0 * 8) * 2;
        uint32_t oA1 = (uint32_t)(r1 * BKP + s1 * 8) * 2;
        cp16(base + 0 * BUF_BYTES + oA0, &g_ahi[(size_t)gr0 * K + k0 + s0 * 8]);
        cp16(base + 0 * BUF_BYTES + oA1, &g_ahi[(size_t)gr1 * K + k0 + s1 * 8]);
        cp16(base + 1 * BUF_BYTES + oA0, &g_alo[(size_t)gr0 * K + k0 + s0 * 8]);
        cp16(base + 1 * BUF_BYTES + oA1, &g_alo[(size_t)gr1 * K + k0 + s1 * 8]);
        cp16(base + 2 * BUF_BYTES + oA0, &g_wthi[(size_t)(bn + r0) * K + k0 + s0 * 8]);
        cp16(base + 2 * BUF_BYTES + oA1, &g_wthi[(size_t)(bn + r1) * K + k0 + s1 * 8]);
        cp16(base + 3 * BUF_BYTES + oA0, &g_wtlo[(size_t)(bn + r0) * K + k0 + s0 * 8]);
        cp16(base + 3 * BUF_BYTES + oA1, &g_wtlo[(size_t)(bn + r1) * K + k0 + s1 * 8]);
        CP_COMMIT();
    };

    issue(0, 0);
    for (int c = 0; c < NCH; c++) {
        const int st = c & 1;
        CP_WAIT0();
        __syncthreads();
        if (c + 1 < NCH) issue(c + 1, st ^ 1);

        uint32_t base = sb + st * STG_BYTES;
        uint32_t bAh = base + 0 * BUF_BYTES;
        uint32_t bAl = base + 1 * BUF_BYTES;
        uint32_t bBh = base + 2 * BUF_BYTES;
        uint32_t bBl = base + 3 * BUF_BYTES;
        #pragma unroll
        for (int ks = 0; ks < 32; ks += 16) {
            uint32_t ah[2][4], al[2][4];
            #pragma unroll
            for (int mt = 0; mt < 2; mt++) {
                uint32_t off = (uint32_t)((a_row + mt * 16) * BKP + ks + a_kof) * 2;
                ldsm_x4(ah[mt], bAh + off);
                ldsm_x4(al[mt], bAl + off);
            }
            #pragma unroll
            for (int nt = 0; nt < 8; nt++) {
                uint32_t off = (uint32_t)((b_row + nt * 8) * BKP + ks + b_kof) * 2;
                uint32_t bh[2], bl[2];
                ldsm_x2(bh, bBh + off);
                ldsm_x2(bl, bBl + off);
                #pragma unroll
                for (int mt = 0; mt < 2; mt++) {
                    mma_bf16(acc[mt][nt], ah[mt], bh);
                    mma_bf16(acc[mt][nt], ah[mt], bl);
                    mma_bf16(acc[mt][nt], al[mt], bh);
                }
            }
        }
        __syncthreads();
    }

    const int er = lane >> 2;
    const int ec = (lane & 3) * 2;
    #pragma unroll
    for (int nt = 0; nt < 8; nt++) {
        int col = bn + warp_n * 64 + nt * 8 + ec;
        float bx = bias[col], by = bias[col + 1];
        #pragma unroll
        for (int mt = 0; mt < 2; mt++) {
            int r = bm + warp_m * 32 + mt * 16 + er;
            if (r < M) {
                float2 o0 = make_float2(acc[mt][nt][0] + bx, acc[mt][nt][1] + by);
                *(float2*)&C[(size_t)r * HID + col] = o0;
            }
            if (r + 8 < M) {
                float2 o1 = make_float2(acc[mt][nt][2] + bx, acc[mt][nt][3] + by);
                *(float2*)&C[(size_t)(r + 8) * HID + col] = o1;
            }
        }
    }
}

// ================= launch =================
extern "C" void kernel_launch(void* const* d_in, const int* in_sizes, int n_in,
                              void* d_out, int out_size) {
    const float* x   = (const float*)d_in[0];
    const int*   ei  = (const int*)d_in[1];
    const float* W1  = (const float*)d_in[2];
    const float* b1  = (const float*)d_in[3];
    const float* W2  = (const float*)d_in[4];
    const float* b2  = (const float*)d_in[5];
    const float* W3  = (const float*)d_in[6];
    const float* b3  = (const float*)d_in[7];
    float*       out = (float*)d_out;

    const int E = in_sizes[1] / 2;
    const int* src = ei;
    const int* dst = ei + E;

    // opt into >48KB dynamic smem (host-side attribute, not a stream op)
    static bool attr_done = false;
    if (!attr_done) {
        cudaFuncSetAttribute(gemm_mma_kernel<128, 1>,  cudaFuncAttributeMaxDynamicSharedMemorySize, GEMM_SMEM);
        cudaFuncSetAttribute(gemm_mma_kernel<256, 1>,  cudaFuncAttributeMaxDynamicSharedMemorySize, GEMM_SMEM);
        cudaFuncSetAttribute(gemm_mma_kernel<256, -1>, cudaFuncAttributeMaxDynamicSharedMemorySize, GEMM_SMEM);
        attr_done = true;
    }

    const int TB = 256;
    const int nb_nodes = (N_NODES + TB - 1) / TB;
    const int nb_edges = (E + TB - 1) / TB;
    const int nb_agg   = (N_NODES * 32 + TB - 1) / TB;
    dim3 gemm_grid((N_NODES + 127) / 128, 2);

    // preprocessing: CSR + dinv (parallel scan)
    init_kernel<<<nb_nodes, TB>>>();
    count_kernel<<<nb_edges, TB>>>(dst, E);
    dinv_kernel<<<nb_nodes, TB>>>();
    scan_reduce_kernel<<<NB_SCAN, 1024>>>();
    scan_part_kernel<<<1, 128>>>();
    scan_apply_kernel<<<NB_SCAN, 1024>>>();
    scatter_kernel<<<nb_edges, TB>>>(src, dst, E);

    // layer 1
    wconv_kernel<<<(HID * 128 + 255) / 256, 256>>>(W1, 128);
    agg_kernel<128, false, -1><<<nb_agg, TB>>>(x);
    gemm_mma_kernel<128, 1><<<gemm_grid, 256, GEMM_SMEM>>>(b1, nullptr);
    // layer 2
    wconv_kernel<<<(HID * 256 + 255) / 256, 256>>>(W2, 256);
    agg_kernel<256, true, 1><<<nb_agg, TB>>>(nullptr);
    gemm_mma_kernel<256, 1><<<gemm_grid, 256, GEMM_SMEM>>>(b2, nullptr);
    // layer 3
    wconv_kernel<<<(HID * 256 + 255) / 256, 256>>>(W3, 256);
    agg_kernel<256, true, 1><<<nb_agg, TB>>>(nullptr);
    gemm_mma_kernel<256, -1><<<gemm_grid, 256, GEMM_SMEM>>>(b3, out);
}

// round 8
// speedup vs baseline: 2.2868x; 1.4380x over previous
#include <cuda_runtime.h>
#include <cuda_bf16.h>
#include <cuda_fp16.h>
#include <cstdint>

#define N_NODES 100000
#define MAX_E   800000
#define HID     256
#define NB_SCAN 98          // ceil(100000/1024)

// ---- scratch (static __device__ globals; no allocation) ----
__device__ __align__(16) __half g_h[(size_t)N_NODES * HID];   // layer output, fp16 (51.2 MB)
__device__ __align__(16) __half g_a[(size_t)N_NODES * HID];   // agg output = GEMM A, fp16
__device__ __align__(16) __half g_wthi[HID * HID];            // W^T hi [256, K] fp16
__device__ __align__(16) __half g_wtlo[HID * HID];            // W^T lo
__device__ float g_dinv[N_NODES];
__device__ int   g_cnt[N_NODES];
__device__ int   g_cur[N_NODES];
__device__ int   g_rowptr[N_NODES + 1];
__device__ int   g_col[MAX_E];
__device__ int   g_part[128];

// ================= PTX helpers (base-target only: ldmatrix/mma/cp.async) =================
__device__ __forceinline__ uint32_t smem_u32(const void* p) {
    uint32_t a;
    asm("{ .reg .u64 t; cvta.to.shared.u64 t, %1; cvt.u32.u64 %0, t; }" : "=r"(a) : "l"(p));
    return a;
}
__device__ __forceinline__ void ldsm_x4(uint32_t* r, uint32_t addr) {
    asm volatile("ldmatrix.sync.aligned.m8n8.x4.shared.b16 {%0,%1,%2,%3}, [%4];"
        : "=r"(r[0]), "=r"(r[1]), "=r"(r[2]), "=r"(r[3]) : "r"(addr));
}
__device__ __forceinline__ void ldsm_x2(uint32_t* r, uint32_t addr) {
    asm volatile("ldmatrix.sync.aligned.m8n8.x2.shared.b16 {%0,%1}, [%2];"
        : "=r"(r[0]), "=r"(r[1]) : "r"(addr));
}
__device__ __forceinline__ void mma_f16(float* c, const uint32_t* a, const uint32_t* b) {
    asm volatile("mma.sync.aligned.m16n8k16.row.col.f32.f16.f16.f32 "
        "{%0,%1,%2,%3}, {%4,%5,%6,%7}, {%8,%9}, {%0,%1,%2,%3};"
        : "+f"(c[0]), "+f"(c[1]), "+f"(c[2]), "+f"(c[3])
        : "r"(a[0]), "r"(a[1]), "r"(a[2]), "r"(a[3]), "r"(b[0]), "r"(b[1]));
}
__device__ __forceinline__ void cp16(uint32_t dst, const void* src) {
    asm volatile("cp.async.cg.shared.global [%0], [%1], 16;" :: "r"(dst), "l"(src));
}
#define CP_COMMIT() asm volatile("cp.async.commit_group;" ::: "memory")
#define CP_WAIT0()  asm volatile("cp.async.wait_group 0;" ::: "memory")

// ================= preprocessing =================
__global__ void init_kernel() {
    int i = blockIdx.x * blockDim.x + threadIdx.x;
    if (i < N_NODES) { g_cnt[i] = 0; g_cur[i] = 0; }
}
__global__ void count_kernel(const int* __restrict__ dst, int E) {
    int e = blockIdx.x * blockDim.x + threadIdx.x;
    if (e < E) {
        int d = dst[e];
        if (d >= 0 && d < N_NODES) atomicAdd(&g_cnt[d], 1);
    }
}
__global__ void dinv_kernel() {
    int i = blockIdx.x * blockDim.x + threadIdx.x;
    if (i < N_NODES) g_dinv[i] = rsqrtf((float)g_cnt[i] + 1.0f);
}
__global__ void scan_reduce_kernel() {
    __shared__ int ws[32];
    int t = threadIdx.x, lane = t & 31, wid = t >> 5;
    int i = blockIdx.x * 1024 + t;
    int v = (i < N_NODES) ? g_cnt[i] : 0;
    #pragma unroll
    for (int o = 16; o > 0; o >>= 1) v += __shfl_down_sync(0xffffffffu, v, o);
    if (lane == 0) ws[wid] = v;
    __syncthreads();
    if (wid == 0) {
        int s = ws[lane];
        #pragma unroll
        for (int o = 16; o > 0; o >>= 1) s += __shfl_down_sync(0xffffffffu, s, o);
        if (lane == 0) g_part[blockIdx.x] = s;
    }
}
__global__ void scan_part_kernel() {
    __shared__ int ws[4];
    int t = threadIdx.x, lane = t & 31, wid = t >> 5;
    int v = (t < NB_SCAN) ? g_part[t] : 0;
    int incl = v;
    #pragma unroll
    for (int o = 1; o < 32; o <<= 1) {
        int n = __shfl_up_sync(0xffffffffu, incl, o);
        if (lane >= o) incl += n;
    }
    if (lane == 31) ws[wid] = incl;
    __syncthreads();
    int off = 0;
    for (int j = 0; j < wid; j++) off += ws[j];
    if (t < NB_SCAN) g_part[t] = off + incl - v;   // exclusive
}
__global__ void scan_apply_kernel() {
    __shared__ int ws[32];
    int t = threadIdx.x, lane = t & 31, wid = t >> 5;
    int i = blockIdx.x * 1024 + t;
    int v = (i < N_NODES) ? g_cnt[i] : 0;
    int incl = v;
    #pragma unroll
    for (int o = 1; o < 32; o <<= 1) {
        int n = __shfl_up_sync(0xffffffffu, incl, o);
        if (lane >= o) incl += n;
    }
    if (lane == 31) ws[wid] = incl;
    __syncthreads();
    if (wid == 0) {
        int wv = ws[lane];
        #pragma unroll
        for (int o = 1; o < 32; o <<= 1) {
            int n = __shfl_up_sync(0xffffffffu, wv, o);
            if (lane >= o) wv += n;
        }
        ws[lane] = wv;
    }
    __syncthreads();
    int pre = (wid > 0) ? ws[wid - 1] : 0;
    if (i < N_NODES) g_rowptr[i + 1] = g_part[blockIdx.x] + pre + incl;
    if (i == 0) g_rowptr[0] = 0;
}
__global__ void scatter_kernel(const int* __restrict__ src,
                               const int* __restrict__ dst, int E) {
    int e = blockIdx.x * blockDim.x + threadIdx.x;
    if (e < E) {
        int d = dst[e];
        int s = src[e];
        if (d >= 0 && d < N_NODES && s >= 0 && s < N_NODES) {
            int p = atomicAdd(&g_cur[d], 1);
            g_col[g_rowptr[d] + p] = s;
        }
    }
}

// ================= W transpose + split-fp16 convert =================
__global__ void wconv_kernel(const float* __restrict__ W, int K) {
    int idx = blockIdx.x * blockDim.x + threadIdx.x;
    if (idx < HID * K) {
        int n = idx / K, k = idx % K;
        float v = W[(size_t)k * HID + n];
        __half h = __float2half_rn(v);
        g_wthi[idx] = h;
        g_wtlo[idx] = __float2half_rn(v - __half2float(h));
    }
}

// ================= aggregation: g_a = fp16(A_norm @ act(in)) =================
// warp-per-node; IN_HALF: input is g_h fp16, else external fp32 (layer 1)
template<int COLS, bool RELU, bool IN_HALF>
__global__ void agg_kernel(const float* __restrict__ in_ext) {
    int gw   = (blockIdx.x * blockDim.x + threadIdx.x) >> 5;
    int lane = threadIdx.x & 31;
    if (gw >= N_NODES) return;
    constexpr int V = COLS / 32;          // elems per lane: 4 (128) or 8 (256)
    float acc[V];
    #pragma unroll
    for (int q = 0; q < V; q++) acc[q] = 0.f;
    const int base = lane * V;
    int rs = __ldg(&g_rowptr[gw]);
    int re = __ldg(&g_rowptr[gw + 1]);

    auto fetch = [&](int s, float vv[V]) {
        if (IN_HALF) {
            const __half* p = g_h + (size_t)s * COLS + base;
            if (V == 8) {
                uint4 raw = *(const uint4*)p;
                const __half2* h2 = reinterpret_cast<const __half2*>(&raw);
                #pragma unroll
                for (int j = 0; j < 4; j++) {
                    float2 f = __half22float2(h2[j]);
                    vv[2 * j] = f.x; vv[2 * j + 1] = f.y;
                }
            } else {
                uint2 raw = *(const uint2*)p;
                const __half2* h2 = reinterpret_cast<const __half2*>(&raw);
                #pragma unroll
                for (int j = 0; j < 2; j++) {
                    float2 f = __half22float2(h2[j]);
                    vv[2 * j] = f.x; vv[2 * j + 1] = f.y;
                }
            }
        } else {
            const float4* p = reinterpret_cast<const float4*>(in_ext + (size_t)s * COLS + base);
            #pragma unroll
            for (int q = 0; q < V / 4; q++) {
                float4 f = p[q];
                vv[q * 4 + 0] = f.x; vv[q * 4 + 1] = f.y;
                vv[q * 4 + 2] = f.z; vv[q * 4 + 3] = f.w;
            }
        }
        if (RELU) {
            #pragma unroll
            for (int q = 0; q < V; q++) vv[q] = fmaxf(vv[q], 0.f);
        }
    };

    int e = rs;
    for (; e + 1 < re; e += 2) {
        int   s0 = g_col[e],   s1 = g_col[e + 1];
        float w0 = g_dinv[s0], w1 = g_dinv[s1];
        float v0[V], v1[V];
        fetch(s0, v0);
        fetch(s1, v1);
        #pragma unroll
        for (int q = 0; q < V; q++) acc[q] += w0 * v0[q] + w1 * v1[q];
    }
    if (e < re) {
        int   s = g_col[e];
        float w = g_dinv[s];
        float v[V];
        fetch(s, v);
        #pragma unroll
        for (int q = 0; q < V; q++) acc[q] += w * v[q];
    }
    float di = g_dinv[gw];
    {
        float v[V];
        fetch(gw, v);
        #pragma unroll
        for (int q = 0; q < V; q++) acc[q] += di * v[q];
    }
    // write fp16
    __half2 o[V / 2];
    #pragma unroll
    for (int q = 0; q < V / 2; q++)
        o[q] = __floats2half2_rn(acc[2 * q] * di, acc[2 * q + 1] * di);
    __half* po = g_a + (size_t)gw * COLS + base;
    if (V == 8)      *(uint4*)po = *(const uint4*)o;
    else             *(uint2*)po = *(const uint2*)o;
}

// ================= HMMA fp16 GEMM (A single, W split hi+lo), cp.async 2-stage =================
// C[M,256] = A @ W + bias; CTA 128x128, BK=32, 8 warps (4m x 2n), warp tile 32x64
#define BKP       40                        // padded K stride (halves): 80 B
#define BUF_BYTES (128 * BKP * 2)           // 10240 B
#define STG_BYTES (3 * BUF_BYTES)           // A, Bh, Bl
#define GEMM_SMEM (2 * STG_BYTES)           // 61440 B

template<int K, bool WRITE_HALF>
__global__ __launch_bounds__(256)
void gemm_mma_kernel(const float* __restrict__ bias, float* __restrict__ C_ext) {
    extern __shared__ __align__(16) char dsm[];
    const int M   = N_NODES;
    const int tid = threadIdx.x;
    const int wid = tid >> 5, lane = tid & 31;
    const int bm  = blockIdx.x * 128;
    const int bn  = blockIdx.y * 128;
    const int warp_m = wid & 3;
    const int warp_n = wid >> 2;
    constexpr int NCH = K / 32;

    const uint32_t sb = smem_u32(dsm);
    const int r0 = tid >> 2, s0 = tid & 3;     // segment slots (2 per thread per buffer)
    const int r1 = r0 + 64;

    float acc[2][8][4];
    #pragma unroll
    for (int mt = 0; mt < 2; mt++)
        #pragma unroll
        for (int nt = 0; nt < 8; nt++)
            #pragma unroll
            for (int q = 0; q < 4; q++) acc[mt][nt][q] = 0.f;

    const int a_row = warp_m * 32 + (lane & 15);
    const int a_kof = (lane >> 4) * 8;
    const int b_row = warp_n * 64 + (lane & 7);
    const int b_kof = ((lane >> 3) & 1) * 8;

    int gr0 = bm + r0; if (gr0 > M - 1) gr0 = M - 1;
    int gr1 = bm + r1; if (gr1 > M - 1) gr1 = M - 1;

    auto issue = [&](int c, int st) {
        const int k0 = c * 32;
        uint32_t base = sb + st * STG_BYTES;
        uint32_t o0 = (uint32_t)(r0 * BKP + s0 * 8) * 2;
        uint32_t o1 = (uint32_t)(r1 * BKP + s0 * 8) * 2;
        cp16(base + 0 * BUF_BYTES + o0, &g_a[(size_t)gr0 * K + k0 + s0 * 8]);
        cp16(base + 0 * BUF_BYTES + o1, &g_a[(size_t)gr1 * K + k0 + s0 * 8]);
        cp16(base + 1 * BUF_BYTES + o0, &g_wthi[(size_t)(bn + r0) * K + k0 + s0 * 8]);
        cp16(base + 1 * BUF_BYTES + o1, &g_wthi[(size_t)(bn + r1) * K + k0 + s0 * 8]);
        cp16(base + 2 * BUF_BYTES + o0, &g_wtlo[(size_t)(bn + r0) * K + k0 + s0 * 8]);
        cp16(base + 2 * BUF_BYTES + o1, &g_wtlo[(size_t)(bn + r1) * K + k0 + s0 * 8]);
        CP_COMMIT();
    };

    issue(0, 0);
    for (int c = 0; c < NCH; c++) {
        const int st = c & 1;
        CP_WAIT0();
        __syncthreads();
        if (c + 1 < NCH) issue(c + 1, st ^ 1);

        uint32_t base = sb + st * STG_BYTES;
        uint32_t bA  = base + 0 * BUF_BYTES;
        uint32_t bBh = base + 1 * BUF_BYTES;
        uint32_t bBl = base + 2 * BUF_BYTES;
        #pragma unroll
        for (int ks = 0; ks < 32; ks += 16) {
            uint32_t af[2][4];
            #pragma unroll
            for (int mt = 0; mt < 2; mt++) {
                uint32_t off = (uint32_t)((a_row + mt * 16) * BKP + ks + a_kof) * 2;
                ldsm_x4(af[mt], bA + off);
            }
            #pragma unroll
            for (int nt = 0; nt < 8; nt++) {
                uint32_t off = (uint32_t)((b_row + nt * 8) * BKP + ks + b_kof) * 2;
                uint32_t bh[2], bl[2];
                ldsm_x2(bh, bBh + off);
                ldsm_x2(bl, bBl + off);
                #pragma unroll
                for (int mt = 0; mt < 2; mt++) {
                    mma_f16(acc[mt][nt], af[mt], bh);
                    mma_f16(acc[mt][nt], af[mt], bl);
                }
            }
        }
        __syncthreads();
    }

    const int er = lane >> 2;
    const int ec = (lane & 3) * 2;
    #pragma unroll
    for (int nt = 0; nt < 8; nt++) {
        int col = bn + warp_n * 64 + nt * 8 + ec;
        float bx = bias[col], by = bias[col + 1];
        #pragma unroll
        for (int mt = 0; mt < 2; mt++) {
            int r = bm + warp_m * 32 + mt * 16 + er;
            if (r < M) {
                float cx = acc[mt][nt][0] + bx, cy = acc[mt][nt][1] + by;
                if (WRITE_HALF) *(__half2*)&g_h[(size_t)r * HID + col] = __floats2half2_rn(cx, cy);
                else            *(float2*)&C_ext[(size_t)r * HID + col] = make_float2(cx, cy);
            }
            if (r + 8 < M) {
                float cx = acc[mt][nt][2] + bx, cy = acc[mt][nt][3] + by;
                if (WRITE_HALF) *(__half2*)&g_h[(size_t)(r + 8) * HID + col] = __floats2half2_rn(cx, cy);
                else            *(float2*)&C_ext[(size_t)(r + 8) * HID + col] = make_float2(cx, cy);
            }
        }
    }
}

// ================= launch =================
extern "C" void kernel_launch(void* const* d_in, const int* in_sizes, int n_in,
                              void* d_out, int out_size) {
    const float* x   = (const float*)d_in[0];
    const int*   ei  = (const int*)d_in[1];
    const float* W1  = (const float*)d_in[2];
    const float* b1  = (const float*)d_in[3];
    const float* W2  = (const float*)d_in[4];
    const float* b2  = (const float*)d_in[5];
    const float* W3  = (const float*)d_in[6];
    const float* b3  = (const float*)d_in[7];
    float*       out = (float*)d_out;

    const int E = in_sizes[1] / 2;
    const int* src = ei;
    const int* dst = ei + E;

    static bool attr_done = false;
    if (!attr_done) {
        cudaFuncSetAttribute(gemm_mma_kernel<128, true>,  cudaFuncAttributeMaxDynamicSharedMemorySize, GEMM_SMEM);
        cudaFuncSetAttribute(gemm_mma_kernel<256, true>,  cudaFuncAttributeMaxDynamicSharedMemorySize, GEMM_SMEM);
        cudaFuncSetAttribute(gemm_mma_kernel<256, false>, cudaFuncAttributeMaxDynamicSharedMemorySize, GEMM_SMEM);
        attr_done = true;
    }

    const int TB = 256;
    const int nb_nodes = (N_NODES + TB - 1) / TB;
    const int nb_edges = (E + TB - 1) / TB;
    const int nb_agg   = (N_NODES * 32 + TB - 1) / TB;
    dim3 gemm_grid((N_NODES + 127) / 128, 2);

    // preprocessing: CSR + dinv (parallel scan)
    init_kernel<<<nb_nodes, TB>>>();
    count_kernel<<<nb_edges, TB>>>(dst, E);
    dinv_kernel<<<nb_nodes, TB>>>();
    scan_reduce_kernel<<<NB_SCAN, 1024>>>();
    scan_part_kernel<<<1, 128>>>();
    scan_apply_kernel<<<NB_SCAN, 1024>>>();
    scatter_kernel<<<nb_edges, TB>>>(src, dst, E);

    // layer 1: agg fp32 x -> g_a fp16; gemm K=128 -> g_h fp16
    wconv_kernel<<<(HID * 128 + 255) / 256, 256>>>(W1, 128);
    agg_kernel<128, false, false><<<nb_agg, TB>>>(x);
    gemm_mma_kernel<128, true><<<gemm_grid, 256, GEMM_SMEM>>>(b1, nullptr);
    // layer 2: agg relu(g_h) -> g_a; gemm K=256 -> g_h
    wconv_kernel<<<(HID * 256 + 255) / 256, 256>>>(W2, 256);
    agg_kernel<256, true, true><<<nb_agg, TB>>>(nullptr);
    gemm_mma_kernel<256, true><<<gemm_grid, 256, GEMM_SMEM>>>(b2, nullptr);
    // layer 3: agg relu(g_h) -> g_a; gemm K=256 -> out (fp32)
    wconv_kernel<<<(HID * 256 + 255) / 256, 256>>>(W3, 256);
    agg_kernel<256, true, true><<<nb_agg, TB>>>(nullptr);
    gemm_mma_kernel<256, false><<<gemm_grid, 256, GEMM_SMEM>>>(b3, out);
}

// round 9
// speedup vs baseline: 2.5951x; 1.1348x over previous
#include <cuda_runtime.h>
#include <cuda_bf16.h>
#include <cuda_fp16.h>
#include <cstdint>

#define N_NODES 100000
#define MAX_E   800000
#define HID     256
#define NB_SCAN 98          // ceil(100000/1024)

// ---- scratch (static __device__ globals; no allocation) ----
__device__ __align__(16) __half g_h[(size_t)N_NODES * HID];   // layer output, fp16 (51.2 MB)
__device__ __align__(16) __half g_a[(size_t)N_NODES * HID];   // agg output = GEMM A, fp16
__device__ __align__(16) __half g_wt[HID * HID];              // W^T [256, K] fp16
__device__ float g_dinv[N_NODES];
__device__ int   g_cnt[N_NODES];
__device__ int   g_cur[N_NODES];
__device__ int   g_rowptr[N_NODES + 1];
__device__ int   g_col[MAX_E];
__device__ int   g_part[128];

// ================= PTX helpers (base-target only: ldmatrix/mma/cp.async) =================
__device__ __forceinline__ uint32_t smem_u32(const void* p) {
    uint32_t a;
    asm("{ .reg .u64 t; cvta.to.shared.u64 t, %1; cvt.u32.u64 %0, t; }" : "=r"(a) : "l"(p));
    return a;
}
__device__ __forceinline__ void ldsm_x4(uint32_t* r, uint32_t addr) {
    asm volatile("ldmatrix.sync.aligned.m8n8.x4.shared.b16 {%0,%1,%2,%3}, [%4];"
        : "=r"(r[0]), "=r"(r[1]), "=r"(r[2]), "=r"(r[3]) : "r"(addr));
}
__device__ __forceinline__ void ldsm_x2(uint32_t* r, uint32_t addr) {
    asm volatile("ldmatrix.sync.aligned.m8n8.x2.shared.b16 {%0,%1}, [%2];"
        : "=r"(r[0]), "=r"(r[1]) : "r"(addr));
}
__device__ __forceinline__ void mma_f16(float* c, const uint32_t* a, const uint32_t* b) {
    asm volatile("mma.sync.aligned.m16n8k16.row.col.f32.f16.f16.f32 "
        "{%0,%1,%2,%3}, {%4,%5,%6,%7}, {%8,%9}, {%0,%1,%2,%3};"
        : "+f"(c[0]), "+f"(c[1]), "+f"(c[2]), "+f"(c[3])
        : "r"(a[0]), "r"(a[1]), "r"(a[2]), "r"(a[3]), "r"(b[0]), "r"(b[1]));
}
__device__ __forceinline__ void cp16(uint32_t dst, const void* src) {
    asm volatile("cp.async.cg.shared.global [%0], [%1], 16;" :: "r"(dst), "l"(src));
}
#define CP_COMMIT() asm volatile("cp.async.commit_group;" ::: "memory")
#define CP_WAIT0()  asm volatile("cp.async.wait_group 0;" ::: "memory")

// ================= preprocessing =================
__global__ void init_kernel() {
    int i = blockIdx.x * blockDim.x + threadIdx.x;
    if (i < N_NODES) { g_cnt[i] = 0; g_cur[i] = 0; }
}
__global__ void count_kernel(const int* __restrict__ dst, int E) {
    int e = blockIdx.x * blockDim.x + threadIdx.x;
    if (e < E) {
        int d = dst[e];
        if (d >= 0 && d < N_NODES) atomicAdd(&g_cnt[d], 1);
    }
}
__global__ void dinv_kernel() {
    int i = blockIdx.x * blockDim.x + threadIdx.x;
    if (i < N_NODES) g_dinv[i] = rsqrtf((float)g_cnt[i] + 1.0f);
}
__global__ void scan_reduce_kernel() {
    __shared__ int ws[32];
    int t = threadIdx.x, lane = t & 31, wid = t >> 5;
    int i = blockIdx.x * 1024 + t;
    int v = (i < N_NODES) ? g_cnt[i] : 0;
    #pragma unroll
    for (int o = 16; o > 0; o >>= 1) v += __shfl_down_sync(0xffffffffu, v, o);
    if (lane == 0) ws[wid] = v;
    __syncthreads();
    if (wid == 0) {
        int s = ws[lane];
        #pragma unroll
        for (int o = 16; o > 0; o >>= 1) s += __shfl_down_sync(0xffffffffu, s, o);
        if (lane == 0) g_part[blockIdx.x] = s;
    }
}
__global__ void scan_part_kernel() {
    __shared__ int ws[4];
    int t = threadIdx.x, lane = t & 31, wid = t >> 5;
    int v = (t < NB_SCAN) ? g_part[t] : 0;
    int incl = v;
    #pragma unroll
    for (int o = 1; o < 32; o <<= 1) {
        int n = __shfl_up_sync(0xffffffffu, incl, o);
        if (lane >= o) incl += n;
    }
    if (lane == 31) ws[wid] = incl;
    __syncthreads();
    int off = 0;
    for (int j = 0; j < wid; j++) off += ws[j];
    if (t < NB_SCAN) g_part[t] = off + incl - v;   // exclusive
}
__global__ void scan_apply_kernel() {
    __shared__ int ws[32];
    int t = threadIdx.x, lane = t & 31, wid = t >> 5;
    int i = blockIdx.x * 1024 + t;
    int v = (i < N_NODES) ? g_cnt[i] : 0;
    int incl = v;
    #pragma unroll
    for (int o = 1; o < 32; o <<= 1) {
        int n = __shfl_up_sync(0xffffffffu, incl, o);
        if (lane >= o) incl += n;
    }
    if (lane == 31) ws[wid] = incl;
    __syncthreads();
    if (wid == 0) {
        int wv = ws[lane];
        #pragma unroll
        for (int o = 1; o < 32; o <<= 1) {
            int n = __shfl_up_sync(0xffffffffu, wv, o);
            if (lane >= o) wv += n;
        }
        ws[lane] = wv;
    }
    __syncthreads();
    int pre = (wid > 0) ? ws[wid - 1] : 0;
    if (i < N_NODES) g_rowptr[i + 1] = g_part[blockIdx.x] + pre + incl;
    if (i == 0) g_rowptr[0] = 0;
}
__global__ void scatter_kernel(const int* __restrict__ src,
                               const int* __restrict__ dst, int E) {
    int e = blockIdx.x * blockDim.x + threadIdx.x;
    if (e < E) {
        int d = dst[e];
        int s = src[e];
        if (d >= 0 && d < N_NODES && s >= 0 && s < N_NODES) {
            int p = atomicAdd(&g_cur[d], 1);
            g_col[g_rowptr[d] + p] = s;
        }
    }
}

// ================= W transpose -> fp16 =================
__global__ void wconv_kernel(const float* __restrict__ W, int K) {
    int idx = blockIdx.x * blockDim.x + threadIdx.x;
    if (idx < HID * K) {
        int n = idx / K, k = idx % K;
        g_wt[idx] = __float2half_rn(W[(size_t)k * HID + n]);
    }
}

// ================= aggregation: g_a = fp16(A_norm @ act(in)) =================
// warp-per-node; IN_HALF: input is g_h fp16, else external fp32 (layer 1)
template<int COLS, bool RELU, bool IN_HALF>
__global__ void agg_kernel(const float* __restrict__ in_ext) {
    int gw   = (blockIdx.x * blockDim.x + threadIdx.x) >> 5;
    int lane = threadIdx.x & 31;
    if (gw >= N_NODES) return;
    constexpr int V = COLS / 32;          // elems per lane: 4 (128) or 8 (256)
    float acc[V];
    #pragma unroll
    for (int q = 0; q < V; q++) acc[q] = 0.f;
    const int base = lane * V;
    int rs = __ldg(&g_rowptr[gw]);
    int re = __ldg(&g_rowptr[gw + 1]);

    auto fetch = [&](int s, float vv[V]) {
        if (IN_HALF) {
            const __half* p = g_h + (size_t)s * COLS + base;
            if (V == 8) {
                uint4 raw = *(const uint4*)p;
                const __half2* h2 = reinterpret_cast<const __half2*>(&raw);
                #pragma unroll
                for (int j = 0; j < 4; j++) {
                    float2 f = __half22float2(h2[j]);
                    vv[2 * j] = f.x; vv[2 * j + 1] = f.y;
                }
            } else {
                uint2 raw = *(const uint2*)p;
                const __half2* h2 = reinterpret_cast<const __half2*>(&raw);
                #pragma unroll
                for (int j = 0; j < 2; j++) {
                    float2 f = __half22float2(h2[j]);
                    vv[2 * j] = f.x; vv[2 * j + 1] = f.y;
                }
            }
        } else {
            const float4* p = reinterpret_cast<const float4*>(in_ext + (size_t)s * COLS + base);
            #pragma unroll
            for (int q = 0; q < V / 4; q++) {
                float4 f = p[q];
                vv[q * 4 + 0] = f.x; vv[q * 4 + 1] = f.y;
                vv[q * 4 + 2] = f.z; vv[q * 4 + 3] = f.w;
            }
        }
        if (RELU) {
            #pragma unroll
            for (int q = 0; q < V; q++) vv[q] = fmaxf(vv[q], 0.f);
        }
    };

    int e = rs;
    // 4-edge unroll: more outstanding gathers
    for (; e + 3 < re; e += 4) {
        int s0 = g_col[e], s1 = g_col[e + 1], s2 = g_col[e + 2], s3 = g_col[e + 3];
        float w0 = g_dinv[s0], w1 = g_dinv[s1], w2 = g_dinv[s2], w3 = g_dinv[s3];
        float v0[V], v1[V], v2[V], v3[V];
        fetch(s0, v0); fetch(s1, v1); fetch(s2, v2); fetch(s3, v3);
        #pragma unroll
        for (int q = 0; q < V; q++)
            acc[q] += (w0 * v0[q] + w1 * v1[q]) + (w2 * v2[q] + w3 * v3[q]);
    }
    for (; e < re; e++) {
        int   s = g_col[e];
        float w = g_dinv[s];
        float v[V];
        fetch(s, v);
        #pragma unroll
        for (int q = 0; q < V; q++) acc[q] += w * v[q];
    }
    float di = g_dinv[gw];
    {
        float v[V];
        fetch(gw, v);
        #pragma unroll
        for (int q = 0; q < V; q++) acc[q] += di * v[q];
    }
    // write fp16
    __half2 o[V / 2];
    #pragma unroll
    for (int q = 0; q < V / 2; q++)
        o[q] = __floats2half2_rn(acc[2 * q] * di, acc[2 * q + 1] * di);
    __half* po = g_a + (size_t)gw * COLS + base;
    if (V == 8)      *(uint4*)po = *(const uint4*)o;
    else             *(uint2*)po = *(const uint2*)o;
}

// ================= HMMA fp16 GEMM (A and W single fp16), cp.async 2-stage =================
// C[M,256] = A @ W + bias; CTA 128x128, BK=32, 8 warps (4m x 2n), warp tile 32x64
#define BKP       40                        // padded K stride (halves): 80 B
#define BUF_BYTES (128 * BKP * 2)           // 10240 B
#define STG_BYTES (2 * BUF_BYTES)           // A, B
#define GEMM_SMEM (2 * STG_BYTES)           // 40960 B -> 2 CTAs/SM

template<int K, bool WRITE_HALF>
__global__ __launch_bounds__(256)
void gemm_mma_kernel(const float* __restrict__ bias, float* __restrict__ C_ext) {
    extern __shared__ __align__(16) char dsm[];
    const int M   = N_NODES;
    const int tid = threadIdx.x;
    const int wid = tid >> 5, lane = tid & 31;
    const int bm  = blockIdx.x * 128;
    const int bn  = blockIdx.y * 128;
    const int warp_m = wid & 3;
    const int warp_n = wid >> 2;
    constexpr int NCH = K / 32;

    const uint32_t sb = smem_u32(dsm);
    const int r0 = tid >> 2, s0 = tid & 3;
    const int r1 = r0 + 64;

    float acc[2][8][4];
    #pragma unroll
    for (int mt = 0; mt < 2; mt++)
        #pragma unroll
        for (int nt = 0; nt < 8; nt++)
            #pragma unroll
            for (int q = 0; q < 4; q++) acc[mt][nt][q] = 0.f;

    const int a_row = warp_m * 32 + (lane & 15);
    const int a_kof = (lane >> 4) * 8;
    const int b_row = warp_n * 64 + (lane & 7);
    const int b_kof = ((lane >> 3) & 1) * 8;

    int gr0 = bm + r0; if (gr0 > M - 1) gr0 = M - 1;
    int gr1 = bm + r1; if (gr1 > M - 1) gr1 = M - 1;

    auto issue = [&](int c, int st) {
        const int k0 = c * 32;
        uint32_t base = sb + st * STG_BYTES;
        uint32_t o0 = (uint32_t)(r0 * BKP + s0 * 8) * 2;
        uint32_t o1 = (uint32_t)(r1 * BKP + s0 * 8) * 2;
        cp16(base + 0 * BUF_BYTES + o0, &g_a[(size_t)gr0 * K + k0 + s0 * 8]);
        cp16(base + 0 * BUF_BYTES + o1, &g_a[(size_t)gr1 * K + k0 + s0 * 8]);
        cp16(base + 1 * BUF_BYTES + o0, &g_wt[(size_t)(bn + r0) * K + k0 + s0 * 8]);
        cp16(base + 1 * BUF_BYTES + o1, &g_wt[(size_t)(bn + r1) * K + k0 + s0 * 8]);
        CP_COMMIT();
    };

    issue(0, 0);
    for (int c = 0; c < NCH; c++) {
        const int st = c & 1;
        CP_WAIT0();
        __syncthreads();
        if (c + 1 < NCH) issue(c + 1, st ^ 1);

        uint32_t base = sb + st * STG_BYTES;
        uint32_t bA = base;
        uint32_t bB = base + BUF_BYTES;
        #pragma unroll
        for (int ks = 0; ks < 32; ks += 16) {
            uint32_t af[2][4];
            #pragma unroll
            for (int mt = 0; mt < 2; mt++) {
                uint32_t off = (uint32_t)((a_row + mt * 16) * BKP + ks + a_kof) * 2;
                ldsm_x4(af[mt], bA + off);
            }
            #pragma unroll
            for (int nt = 0; nt < 8; nt++) {
                uint32_t off = (uint32_t)((b_row + nt * 8) * BKP + ks + b_kof) * 2;
                uint32_t bf[2];
                ldsm_x2(bf, bB + off);
                #pragma unroll
                for (int mt = 0; mt < 2; mt++)
                    mma_f16(acc[mt][nt], af[mt], bf);
            }
        }
        __syncthreads();
    }

    const int er = lane >> 2;
    const int ec = (lane & 3) * 2;
    #pragma unroll
    for (int nt = 0; nt < 8; nt++) {
        int col = bn + warp_n * 64 + nt * 8 + ec;
        float bx = bias[col], by = bias[col + 1];
        #pragma unroll
        for (int mt = 0; mt < 2; mt++) {
            int r = bm + warp_m * 32 + mt * 16 + er;
            if (r < M) {
                float cx = acc[mt][nt][0] + bx, cy = acc[mt][nt][1] + by;
                if (WRITE_HALF) *(__half2*)&g_h[(size_t)r * HID + col] = __floats2half2_rn(cx, cy);
                else            *(float2*)&C_ext[(size_t)r * HID + col] = make_float2(cx, cy);
            }
            if (r + 8 < M) {
                float cx = acc[mt][nt][2] + bx, cy = acc[mt][nt][3] + by;
                if (WRITE_HALF) *(__half2*)&g_h[(size_t)(r + 8) * HID + col] = __floats2half2_rn(cx, cy);
                else            *(float2*)&C_ext[(size_t)(r + 8) * HID + col] = make_float2(cx, cy);
            }
        }
    }
}

// ================= launch =================
extern "C" void kernel_launch(void* const* d_in, const int* in_sizes, int n_in,
                              void* d_out, int out_size) {
    const float* x   = (const float*)d_in[0];
    const int*   ei  = (const int*)d_in[1];
    const float* W1  = (const float*)d_in[2];
    const float* b1  = (const float*)d_in[3];
    const float* W2  = (const float*)d_in[4];
    const float* b2  = (const float*)d_in[5];
    const float* W3  = (const float*)d_in[6];
    const float* b3  = (const float*)d_in[7];
    float*       out = (float*)d_out;

    const int E = in_sizes[1] / 2;
    const int* src = ei;
    const int* dst = ei + E;

    static bool attr_done = false;
    if (!attr_done) {
        cudaFuncSetAttribute(gemm_mma_kernel<128, true>,  cudaFuncAttributeMaxDynamicSharedMemorySize, GEMM_SMEM);
        cudaFuncSetAttribute(gemm_mma_kernel<256, true>,  cudaFuncAttributeMaxDynamicSharedMemorySize, GEMM_SMEM);
        cudaFuncSetAttribute(gemm_mma_kernel<256, false>, cudaFuncAttributeMaxDynamicSharedMemorySize, GEMM_SMEM);
        attr_done = true;
    }

    const int TB = 256;
    const int nb_nodes = (N_NODES + TB - 1) / TB;
    const int nb_edges = (E + TB - 1) / TB;
    const int nb_agg   = (N_NODES * 32 + TB - 1) / TB;
    dim3 gemm_grid((N_NODES + 127) / 128, 2);

    // preprocessing: CSR + dinv (parallel scan)
    init_kernel<<<nb_nodes, TB>>>();
    count_kernel<<<nb_edges, TB>>>(dst, E);
    dinv_kernel<<<nb_nodes, TB>>>();
    scan_reduce_kernel<<<NB_SCAN, 1024>>>();
    scan_part_kernel<<<1, 128>>>();
    scan_apply_kernel<<<NB_SCAN, 1024>>>();
    scatter_kernel<<<nb_edges, TB>>>(src, dst, E);

    // layer 1: agg fp32 x -> g_a fp16; gemm K=128 -> g_h fp16
    wconv_kernel<<<(HID * 128 + 255) / 256, 256>>>(W1, 128);
    agg_kernel<128, false, false><<<nb_agg, TB>>>(x);
    gemm_mma_kernel<128, true><<<gemm_grid, 256, GEMM_SMEM>>>(b1, nullptr);
    // layer 2: agg relu(g_h) -> g_a; gemm K=256 -> g_h
    wconv_kernel<<<(HID * 256 + 255) / 256, 256>>>(W2, 256);
    agg_kernel<256, true, true><<<nb_agg, TB>>>(nullptr);
    gemm_mma_kernel<256, true><<<gemm_grid, 256, GEMM_SMEM>>>(b2, nullptr);
    // layer 3: agg relu(g_h) -> g_a; gemm K=256 -> out (fp32)
    wconv_kernel<<<(HID * 256 + 255) / 256, 256>>>(W3, 256);
    agg_kernel<256, true, true><<<nb_agg, TB>>>(nullptr);
    gemm_mma_kernel<256, false><<<gemm_grid, 256, GEMM_SMEM>>>(b3, out);
}